// round 16
// baseline (speedup 1.0000x reference)
#include <cuda_runtime.h>
#include <cstdint>

#define TBK   128
#define NTH   256
#define HID   128
#define NEXP  64
#define WST   68        // Wt row stride (u32 words)
#define LST   68        // logits row stride (fp32 words)
#define NEGINF (__int_as_float(0xff800000u))

// ---- smem word offsets ----
#define SW_L     0                    // fp32 [128][68] raw logits -> exps
#define SW_XC    0                    // A staging overlays L: [8 warps][3 stages][16 rows][20 w]
#define SW_WT    8704                 // u32 2 x [64][68] bf16-pair terms
#define SW_ZINV  17408                // fp32 [128]
#define SW_CNT   17536                // int [64]
#define SW_LASTF 17600                // int
#define SW_RS    17604                // fp32 [8][64] recompute scratch
#define SW_TOTAL 18116
#define SW_PART  8704                 // overlay on Wt
#define SW_DTERM 9216                 // overlay on Wt (byte 36864)

__device__ unsigned long long g_scoreFix[NEXP];
__device__ int g_cnt[NEXP];
__device__ int g_sync;

__device__ __forceinline__ uint32_t f2bf2(float lo, float hi) {
    uint32_t r;
    asm("cvt.rn.bf16x2.f32 %0, %1, %2;" : "=r"(r) : "f"(hi), "f"(lo));
    return r;
}
__device__ __forceinline__ float bflo(uint32_t p) { return __uint_as_float(p << 16); }
__device__ __forceinline__ float bfhi(uint32_t p) { return __uint_as_float(p & 0xFFFF0000u); }

__device__ __forceinline__ uint32_t smem_u32(const void* p) {
    uint32_t a;
    asm("{ .reg .u64 t; cvta.to.shared.u64 t, %1; cvt.u32.u64 %0, t; }" : "=r"(a) : "l"(p));
    return a;
}
__device__ __forceinline__ void cpasync16(uint32_t dst, const void* src) {
    asm volatile("cp.async.cg.shared.global [%0], [%1], 16;" :: "r"(dst), "l"(src) : "memory");
}

__device__ __forceinline__ void mma16816(float* d, const uint32_t* a, uint32_t b0, uint32_t b1) {
    asm volatile(
        "mma.sync.aligned.m16n8k16.row.col.f32.bf16.bf16.f32 "
        "{%0,%1,%2,%3}, {%4,%5,%6,%7}, {%8,%9}, {%0,%1,%2,%3};"
        : "+f"(d[0]), "+f"(d[1]), "+f"(d[2]), "+f"(d[3])
        : "r"(a[0]), "r"(a[1]), "r"(a[2]), "r"(a[3]), "r"(b0), "r"(b1));
}
__device__ __forceinline__ void mma_zc(float* d, const uint32_t* a, uint32_t b0, uint32_t b1) {
    asm volatile(
        "mma.sync.aligned.m16n8k16.row.col.f32.bf16.bf16.f32 "
        "{%0,%1,%2,%3}, {%4,%5,%6,%7}, {%8,%9}, {%10,%10,%10,%10};"
        : "=f"(d[0]), "=f"(d[1]), "=f"(d[2]), "=f"(d[3])
        : "r"(a[0]), "r"(a[1]), "r"(a[2]), "r"(a[3]), "r"(b0), "r"(b1), "f"(0.f));
}

// order-preserving float->uint key with expert idx in low 6 bits (max => lower idx on tie)
__device__ __forceinline__ uint32_t packkey(float f, int gi) {
    uint32_t b = __float_as_uint(f);
    uint32_t m = 0x80000000u | (uint32_t)((int)b >> 31);
    return ((b ^ m) & 0xFFFFFFC0u) | (uint32_t)(63 - gi);
}

// ---- exact float path (rare, flagged warps only) ----
__device__ __forceinline__ int find_top32(const float (&v)[32], unsigned mask, float& mval) {
    float w[16];
#pragma unroll
    for (int i = 0; i < 16; ++i) {
        float x0 = ((mask >> (2 * i)) & 1u)     ? NEGINF : v[2 * i];
        float x1 = ((mask >> (2 * i + 1)) & 1u) ? NEGINF : v[2 * i + 1];
        w[i] = fmaxf(x0, x1);
    }
#pragma unroll
    for (int n = 8; n >= 1; n >>= 1)
#pragma unroll
        for (int i = 0; i < n; ++i) w[i] = fmaxf(w[2 * i], w[2 * i + 1]);
    float m = w[0];
    int b0 = 32, b1 = 32;
#pragma unroll
    for (int i = 15; i >= 0; --i) {
        float y0 = ((mask >> i) & 1u) ? NEGINF : v[i];
        if (y0 == m) b0 = i;
        float y1 = ((mask >> (i + 16)) & 1u) ? NEGINF : v[i + 16];
        if (y1 == m) b1 = i + 16;
    }
    mval = m;
    return (b0 < 32) ? b0 : b1;
}
__device__ __forceinline__ void select_top7f(const float (&v)[32], int h,
                                             float (&tv)[7], int (&ti)[7]) {
    unsigned mask = 0;
    float lv[7]; int li[7];
#pragma unroll
    for (int p = 0; p < 7; ++p) {
        li[p] = find_top32(v, mask, lv[p]);
        mask |= 1u << li[p];
        li[p] += h * 32;
    }
    float ov[7]; int oi[7];
#pragma unroll
    for (int p = 0; p < 7; ++p) {
        ov[p] = __shfl_xor_sync(0xffffffffu, lv[p], 1);
        oi[p] = __shfl_xor_sync(0xffffffffu, li[p], 1);
    }
    float av[7], bv[7]; int ai[7], bi[7];
#pragma unroll
    for (int p = 0; p < 7; ++p) {
        av[p] = h ? ov[p] : lv[p];  ai[p] = h ? oi[p] : li[p];
        bv[p] = h ? lv[p] : ov[p];  bi[p] = h ? li[p] : oi[p];
    }
#pragma unroll
    for (int p = 0; p < 7; ++p) {
        bool ta = av[0] >= bv[0];
        tv[p] = ta ? av[0] : bv[0];
        ti[p] = ta ? ai[0] : bi[0];
        if (ta) {
            av[0]=av[1]; av[1]=av[2]; av[2]=av[3]; av[3]=av[4]; av[4]=av[5]; av[5]=av[6]; av[6]=NEGINF;
            ai[0]=ai[1]; ai[1]=ai[2]; ai[2]=ai[3]; ai[3]=ai[4]; ai[4]=ai[5]; ai[5]=ai[6];
        } else {
            bv[0]=bv[1]; bv[1]=bv[2]; bv[2]=bv[3]; bv[3]=bv[4]; bv[4]=bv[5]; bv[5]=bv[6]; bv[6]=NEGINF;
            bi[0]=bi[1]; bi[1]=bi[2]; bi[2]=bi[3]; bi[3]=bi[4]; bi[4]=bi[5]; bi[5]=bi[6];
        }
    }
}

extern __shared__ float smf[];

__global__ __launch_bounds__(NTH, 3)
void moe_main(const float* __restrict__ x, const float* __restrict__ W,
              float* __restrict__ out, int N) {
    const int tid  = threadIdx.x;
    const int wid  = tid >> 5;
    const int lane = tid & 31;
    const long long blk = blockIdx.x;

    float*    L     = smf + SW_L;
    uint32_t* Wt    = reinterpret_cast<uint32_t*>(smf + SW_WT);
    float*    zinv  = smf + SW_ZINV;
    int*      cntS  = reinterpret_cast<int*>(smf + SW_CNT);
    int*      lastF = reinterpret_cast<int*>(smf + SW_LASTF);
    float*    rescr = smf + SW_RS;
    float*    part  = smf + SW_PART;
    double*   dterm = reinterpret_cast<double*>(smf + SW_DTERM);
    const uint32_t sbase = smem_u32(smf);

    const int m0 = wid * 16;
    const float* gx = x + blk * (long long)(TBK * HID) + (long long)m0 * HID;
    const uint32_t xcb = sbase + (uint32_t)(SW_XC + wid * 960) * 4u;  // warp staging base (bytes)
    const int r2  = lane >> 1;              // staging row 0..15
    const int q2  = (lane & 1) * 2;         // quarter base 0/2

    // ---- prologue: issue A stages for s=0,1,2 (overlaps W staging) ----
#pragma unroll
    for (int ps = 0; ps < 3; ++ps) {
        const float* src = gx + r2 * HID + 16 * ps + q2 * 4;
        uint32_t dst = xcb + (uint32_t)ps * 1280u + (uint32_t)(r2 * 80 + q2 * 16);
        cpasync16(dst, src);
        cpasync16(dst + 16, src + 4);
        asm volatile("cp.async.commit_group;" ::: "memory");
    }

    // ---- stage W: 2 bf16-pair terms ----
    {
        int e  = tid >> 2;
        int kq = (tid & 3) * 32;
        float wv[32];
        const float4* gw = reinterpret_cast<const float4*>(W + e * HID + kq);
#pragma unroll
        for (int j = 0; j < 8; ++j) {
            float4 g = gw[j];
            wv[4 * j] = g.x; wv[4 * j + 1] = g.y; wv[4 * j + 2] = g.z; wv[4 * j + 3] = g.w;
        }
#pragma unroll
        for (int term = 0; term < 2; ++term) {
            uint32_t pk[16];
#pragma unroll
            for (int j = 0; j < 16; ++j) {
                pk[j] = f2bf2(wv[2 * j], wv[2 * j + 1]);
                if (term == 0) {
                    wv[2 * j]     -= bflo(pk[j]);
                    wv[2 * j + 1] -= bfhi(pk[j]);
                }
            }
            uint32_t* dst = Wt + term * (NEXP * WST) + e * WST + (tid & 3) * 16;
#pragma unroll
            for (int u = 0; u < 4; ++u)
                *reinterpret_cast<uint4*>(dst + 4 * u) =
                    make_uint4(pk[4 * u], pk[4 * u + 1], pk[4 * u + 2], pk[4 * u + 3]);
        }
    }
    if (tid < NEXP) cntS[tid] = 0;
    __syncthreads();

    // ---- GEMM with per-warp 3-stage A pipeline ----
    const int g  = lane >> 2;
    const int tg = lane & 3;

    float accM[8][4];
#pragma unroll
    for (int t = 0; t < 8; ++t)
#pragma unroll
        for (int i = 0; i < 4; ++i) accM[t][i] = 0.f;

    const uint32_t* WtB = Wt + g * WST;

#pragma unroll
    for (int s = 0; s < 8; ++s) {
        if (s < 6)      asm volatile("cp.async.wait_group 2;" ::: "memory");
        else if (s == 6) asm volatile("cp.async.wait_group 1;" ::: "memory");
        else            asm volatile("cp.async.wait_group 0;" ::: "memory");
        __syncwarp();

        const float* xsw = smf + SW_XC + wid * 960 + (s % 3) * 320;
        float2 x00 = *reinterpret_cast<const float2*>(xsw + g * 20 + tg * 2);
        float2 x01 = *reinterpret_cast<const float2*>(xsw + g * 20 + tg * 2 + 8);
        float2 x10 = *reinterpret_cast<const float2*>(xsw + (g + 8) * 20 + tg * 2);
        float2 x11 = *reinterpret_cast<const float2*>(xsw + (g + 8) * 20 + tg * 2 + 8);

        uint32_t A0[4], A1[4];
        A0[0] = f2bf2(x00.x, x00.y); A0[1] = f2bf2(x10.x, x10.y);
        A0[2] = f2bf2(x01.x, x01.y); A0[3] = f2bf2(x11.x, x11.y);
        x00.x -= bflo(A0[0]); x00.y -= bfhi(A0[0]);
        x10.x -= bflo(A0[1]); x10.y -= bfhi(A0[1]);
        x01.x -= bflo(A0[2]); x01.y -= bfhi(A0[2]);
        x11.x -= bflo(A0[3]); x11.y -= bfhi(A0[3]);
        A1[0] = f2bf2(x00.x, x00.y); A1[1] = f2bf2(x10.x, x10.y);
        A1[2] = f2bf2(x01.x, x01.y); A1[3] = f2bf2(x11.x, x11.y);

        const int bp = 8 * s + tg;
#pragma unroll
        for (int t = 0; t < 8; ++t) {
            const uint32_t* r0 = WtB + (8 * t) * WST + bp;
            uint32_t B00 = r0[0],          B01 = r0[4];
            uint32_t B10 = r0[NEXP * WST], B11 = r0[NEXP * WST + 4];
            float tm[4], tc[4];
            mma_zc(tm, A0, B00, B01);
            mma_zc(tc, A0, B10, B11);
            mma16816(tc, A1, B00, B01);
            mma16816(tc, A1, B10, B11);
            accM[t][0] += tm[0] + tc[0];
            accM[t][1] += tm[1] + tc[1];
            accM[t][2] += tm[2] + tc[2];
            accM[t][3] += tm[3] + tc[3];
        }

        if (s < 5) {   // issue stage s+3 into ring slot (s%3), just consumed
            const float* src = gx + r2 * HID + 16 * (s + 3) + q2 * 4;
            uint32_t dst = xcb + (uint32_t)((s + 3) % 3) * 1280u + (uint32_t)(r2 * 80 + q2 * 16);
            cpasync16(dst, src);
            cpasync16(dst + 16, src + 4);
            asm volatile("cp.async.commit_group;" ::: "memory");
        }
    }
    __syncthreads();   // all warps' stages consumed; L may overlay staging now

    // ---- scatter logits to L[token][expert] ----
#pragma unroll
    for (int t = 0; t < 8; ++t) {
        int col = 8 * t + tg * 2;
        *reinterpret_cast<float2*>(L + (m0 + g) * LST + col)     = make_float2(accM[t][0], accM[t][1]);
        *reinterpret_cast<float2*>(L + (m0 + g + 8) * LST + col) = make_float2(accM[t][2], accM[t][3]);
    }
    __syncthreads();

    // ---- epilogue: 2 threads/token, packed-int top-k ----
    {
        const int t = tid >> 1;
        const int h = tid & 1;
        const int warpE = wid;

        uint32_t key[32];
#pragma unroll
        for (int j = 0; j < 8; ++j) {
            float4 q = *reinterpret_cast<const float4*>(L + t * LST + h * 32 + 4 * j);
            key[4 * j]     = packkey(q.x, 4 * j     + 32 * h);
            key[4 * j + 1] = packkey(q.y, 4 * j + 1 + 32 * h);
            key[4 * j + 2] = packkey(q.z, 4 * j + 2 + 32 * h);
            key[4 * j + 3] = packkey(q.w, 4 * j + 3 + 32 * h);
        }

        uint32_t lw[7];
#pragma unroll
        for (int p = 0; p < 7; ++p) {
            uint32_t w16[16];
#pragma unroll
            for (int i = 0; i < 16; ++i) w16[i] = max(key[2 * i], key[2 * i + 1]);
#pragma unroll
            for (int n = 8; n >= 1; n >>= 1)
#pragma unroll
                for (int i = 0; i < n; ++i) w16[i] = max(w16[2 * i], w16[2 * i + 1]);
            lw[p] = w16[0];
            if (p < 6) {
#pragma unroll
                for (int i = 0; i < 32; ++i) key[i] = (key[i] == lw[p]) ? 0u : key[i];
            }
        }

        // pair merge (keys unique -> plain int compare keeps exact tie semantics)
        uint32_t av[7], bv[7];
#pragma unroll
        for (int p = 0; p < 7; ++p) {
            av[p] = lw[p];
            bv[p] = __shfl_xor_sync(0xffffffffu, lw[p], 1);
        }
        uint32_t mw[7];
#pragma unroll
        for (int p = 0; p < 7; ++p) {
            bool ta = av[0] > bv[0];
            mw[p] = ta ? av[0] : bv[0];
            if (ta) {
                av[0]=av[1]; av[1]=av[2]; av[2]=av[3]; av[3]=av[4]; av[4]=av[5]; av[5]=av[6]; av[6]=0u;
            } else {
                bv[0]=bv[1]; bv[1]=bv[2]; bv[2]=bv[3]; bv[3]=bv[4]; bv[4]=bv[5]; bv[5]=bv[6]; bv[6]=0u;
            }
        }

        int ti[7];
        bool flg = false;
        float prevv = 0.f;
#pragma unroll
        for (int p = 0; p < 7; ++p) {
            ti[p] = 63 - (int)(mw[p] & 63u);
            uint32_t kb = mw[p] & 0xFFFFFFC0u;
            uint32_t fb = (kb & 0x80000000u) ? (kb ^ 0x80000000u) : ~kb;
            float va = __uint_as_float(fb);
            if (p) flg |= (prevv - va) < 7e-5f;   // covers HMMA err + 63-ulp packing
            prevv = va;
        }

        unsigned fmsk = __ballot_sync(0xffffffffu, flg);
        if (fmsk) {
            // exact fp32 recompute of flagged tokens; write exact logits back to L
            unsigned em = fmsk & 0x55555555u;
            float* rs = rescr + warpE * 64;
            while (em) {
                int src = __ffs(em) - 1;
                em &= em - 1;
                int tsrc = warpE * 16 + (src >> 1);
                long long gtok = blk * TBK + tsrc;
                const float* xrow = x + gtok * HID;
                const float* w0 = W + (2 * lane) * HID;
                float a0 = 0.f, a1 = 0.f;
#pragma unroll 8
                for (int k = 0; k < HID; ++k) {
                    float xv = __ldg(xrow + k);
                    a0 = fmaf(xv, __ldg(w0 + k), a0);
                    a1 = fmaf(xv, __ldg(w0 + HID + k), a1);
                }
                rs[2 * lane] = a0;
                rs[2 * lane + 1] = a1;
                __syncwarp();
                L[tsrc * LST + 2 * lane]     = rs[2 * lane];
                L[tsrc * LST + 2 * lane + 1] = rs[2 * lane + 1];
                __syncwarp();
            }
            // exact float selection for the whole warp (rare path)
            float v[32];
#pragma unroll
            for (int j = 0; j < 8; ++j) {
                float4 q = *reinterpret_cast<const float4*>(L + t * LST + h * 32 + 4 * j);
                v[4 * j] = q.x; v[4 * j + 1] = q.y; v[4 * j + 2] = q.z; v[4 * j + 3] = q.w;
            }
            float tvf[7];
            select_top7f(v, h, tvf, ti);
        }

        // exact values for m1 / weights straight from L (still raw logits)
        float m1 = L[t * LST + ti[0]];
        float ev[6];
        if (h == 0) {
#pragma unroll
            for (int p = 0; p < 6; ++p) ev[p] = L[t * LST + ti[p]];
        }
        __syncwarp();

        float Zh = 0.f;
#pragma unroll
        for (int j = 0; j < 8; ++j) {
            float4 q = *reinterpret_cast<const float4*>(L + t * LST + h * 32 + 4 * j);
            float e0 = __expf(q.x - m1);
            float e1 = __expf(q.y - m1);
            float e2 = __expf(q.z - m1);
            float e3 = __expf(q.w - m1);
            Zh += (e0 + e1) + (e2 + e3);
            *reinterpret_cast<float4*>(L + t * LST + h * 32 + 4 * j) =
                make_float4(e0, e1, e2, e3);
        }
        float Z = Zh + __shfl_xor_sync(0xffffffffu, Zh, 1);

        if (h == 0) {
            zinv[t] = 1.f / Z;
            float E6 = 0.f;
#pragma unroll
            for (int p = 0; p < 6; ++p) { ev[p] = __expf(ev[p] - m1); E6 += ev[p]; }
            float invd = 1.f / (E6 + 1e-20f * Z);   // == ref renormalization exactly

            size_t gt = (size_t)blk * TBK + t;
            float* oi = out + gt * 6;
            float* ow = out + (size_t)N * 6 + gt * 6;
#pragma unroll
            for (int p = 0; p < 6; ++p) {
                oi[p] = (float)ti[p];
                ow[p] = ev[p] * invd;
                atomicAdd(&cntS[ti[p]], 1);
            }
        }
    }
    __syncthreads();

    // ---- Pi column sums ----
    {
        int e = tid & 63;
        int q = tid >> 6;
        float s0 = 0.f, s1 = 0.f;
#pragma unroll
        for (int j = 0; j < 32; j += 2) {
            int t0 = q * 32 + j;
            s0 = fmaf(L[(t0 + 0) * LST + e], zinv[t0 + 0], s0);
            s1 = fmaf(L[(t0 + 1) * LST + e], zinv[t0 + 1], s1);
        }
        part[q * 64 + e] = s0 + s1;
    }
    __syncthreads();

    if (tid < NEXP) {
        float s = ((part[tid] + part[64 + tid]) + (part[128 + tid] + part[192 + tid]));
        atomicAdd(&g_scoreFix[tid], (unsigned long long)(s * 1073741824.0f)); // *2^30
        atomicAdd(&g_cnt[tid], cntS[tid]);
    }
    __syncthreads();

    // ---- last-block finalize ----
    if (tid == 0) {
        __threadfence();
        int r = atomicAdd(&g_sync, 1);
        lastF[0] = (r == (int)gridDim.x - 1) ? 1 : 0;
    }
    __syncthreads();
    if (lastF[0]) {
        __threadfence();
        if (tid < NEXP) {
            double invN = 1.0 / (double)N;
            double Pi = (double)g_scoreFix[tid] * (1.0 / 1073741824.0) * invN;
            double fi = (double)g_cnt[tid] * 64.0 / ((double)N * 6.0);
            dterm[tid] = Pi * fi;
            g_scoreFix[tid] = 0ull;
            g_cnt[tid]      = 0;
        }
        __syncthreads();
        if (tid == 0) {
            double aux = 0.0;
            for (int e = 0; e < NEXP; ++e) aux += dterm[e];
            out[(size_t)N * 12] = (float)(aux * 1e-3);
            g_sync = 0;
        }
    }
}

extern "C" void kernel_launch(void* const* d_in, const int* in_sizes, int n_in,
                              void* d_out, int out_size) {
    const float* x = (const float*)d_in[0];
    const float* W = (const float*)d_in[1];
    int N = in_sizes[0] / HID;

    int smem_bytes = SW_TOTAL * (int)sizeof(float) + 128;
    cudaFuncSetAttribute(moe_main, cudaFuncAttributeMaxDynamicSharedMemorySize, smem_bytes);
    moe_main<<<N / TBK, NTH, smem_bytes>>>(x, W, (float*)d_out, N);
}